// round 5
// baseline (speedup 1.0000x reference)
#include <cuda_runtime.h>
#include <cuda_bf16.h>
#include <cstdint>

#define N_NODES 50000
#define N_EDGES 800000
#define IN_DIM  128
#define OUT_DIM 128
#define EDGE_DIM 64
#define NTILES  (N_EDGES / 128)   // 6250
#define GRID_E  148

typedef unsigned long long u64;

// Scratch for node projections (allocation-free per harness rules).
__device__ __align__(16) float g_HU[(size_t)N_NODES * OUT_DIM];
__device__ __align__(16) float g_HW[(size_t)N_NODES * OUT_DIM];
__device__ int g_idx_is64;

// ----------------------- index dtype detection ------------------------------
__global__ void detect_idx_kernel(const int* __restrict__ ei32) {
    if (threadIdx.x == 0 && blockIdx.x == 0) {
        int all_zero = 1;
        for (int i = 0; i < 256; ++i)
            if (ei32[2 * i + 1] != 0) { all_zero = 0; break; }
        g_idx_is64 = all_zero;
    }
}
__device__ __forceinline__ int fetch_idx(const int* __restrict__ ei32,
                                         int is64, size_t pos) {
    int v = is64 ? ei32[2 * pos] : ei32[pos];
    v = v < 0 ? 0 : (v >= N_NODES ? N_NODES - 1 : v);
    return v;
}

// split f32 pair -> bf16x2 hi word + bf16x2 lo word
__device__ __forceinline__ void cvt_split(float x, float y, uint32_t& hi, uint32_t& lo) {
    __nv_bfloat162 h = __floats2bfloat162_rn(x, y);
    float hx = __bfloat162float(h.x), hy = __bfloat162float(h.y);
    __nv_bfloat162 l = __floats2bfloat162_rn(x - hx, y - hy);
    hi = *reinterpret_cast<uint32_t*>(&h);
    lo = *reinterpret_cast<uint32_t*>(&l);
}

__device__ __forceinline__ void mma16816(float* c, const uint32_t* a,
                                         uint32_t b0, uint32_t b1) {
    asm volatile(
        "mma.sync.aligned.m16n8k16.row.col.f32.bf16.bf16.f32 "
        "{%0,%1,%2,%3}, {%4,%5,%6,%7}, {%8,%9}, {%0,%1,%2,%3};"
        : "+f"(c[0]), "+f"(c[1]), "+f"(c[2]), "+f"(c[3])
        : "r"(a[0]), "r"(a[1]), "r"(a[2]), "r"(a[3]), "r"(b0), "r"(b1));
}

// ---------------------------------------------------------------------------
// Node projection (fp32 f32x2 path — unchanged from R3, passes exactly)
// ---------------------------------------------------------------------------
__device__ __forceinline__ u64 pack2(float lo, float hi) {
    u64 r; asm("mov.b64 %0, {%1, %2};" : "=l"(r) : "f"(lo), "f"(hi)); return r;
}
__device__ __forceinline__ void fma2(u64& d, u64 a, u64 b) {
    asm("fma.rn.f32x2 %0, %1, %2, %3;" : "=l"(d) : "l"(a), "l"(b), "l"(d));
}
__device__ __forceinline__ float2 unpack2(u64 v) {
    float2 f; asm("mov.b64 {%0, %1}, %2;" : "=f"(f.x), "=f"(f.y) : "l"(v)); return f;
}

__global__ __launch_bounds__(256, 2)
void node_proj_kernel(const float* __restrict__ h,
                      const float* __restrict__ Whu,
                      const float* __restrict__ Whw)
{
    __shared__ __align__(16) float Wsh[32][132];
    __shared__ __align__(16) float Hsh[32][132];

    const float* __restrict__ W   = blockIdx.y ? Whw : Whu;
    float*       __restrict__ dst = blockIdx.y ? g_HW : g_HU;

    const int tid = threadIdx.x;
    const int tx  = tid & 31;
    const int ty  = tid >> 5;
    const int n0  = blockIdx.x * 128;

    u64 acc[8][4];
#pragma unroll
    for (int p = 0; p < 8; ++p)
#pragma unroll
        for (int j = 0; j < 4; ++j) acc[p][j] = 0ULL;

#pragma unroll 1
    for (int s = 0; s < 4; ++s) {
        __syncthreads();
#pragma unroll
        for (int it = 0; it < 4; ++it) {
            int idx = it * 256 + tid;
            int o   = idx >> 3;
            int kq  = idx & 7;
            float4 w = *reinterpret_cast<const float4*>(W + (size_t)o * IN_DIM + s * 32 + kq * 4);
            Wsh[kq * 4 + 0][o] = w.x; Wsh[kq * 4 + 1][o] = w.y;
            Wsh[kq * 4 + 2][o] = w.z; Wsh[kq * 4 + 3][o] = w.w;
        }
#pragma unroll
        for (int it = 0; it < 4; ++it) {
            int idx = it * 256 + tid;
            int ln  = idx >> 3;
            int kq  = idx & 7;
            int n   = n0 + ln;
            float4 v = make_float4(0.f, 0.f, 0.f, 0.f);
            if (n < N_NODES)
                v = *reinterpret_cast<const float4*>(h + (size_t)n * IN_DIM + s * 32 + kq * 4);
            Hsh[kq * 4 + 0][ln] = v.x; Hsh[kq * 4 + 1][ln] = v.y;
            Hsh[kq * 4 + 2][ln] = v.z; Hsh[kq * 4 + 3][ln] = v.w;
        }
        __syncthreads();

#pragma unroll
        for (int k = 0; k < 32; ++k) {
            float4 w = *reinterpret_cast<const float4*>(&Wsh[k][tx * 4]);
            u64 w2[4];
            w2[0] = pack2(w.x, w.x); w2[1] = pack2(w.y, w.y);
            w2[2] = pack2(w.z, w.z); w2[3] = pack2(w.w, w.w);
            u64 ev[8];
#pragma unroll
            for (int q = 0; q < 4; ++q) {
                ulonglong2 ep = *reinterpret_cast<const ulonglong2*>(&Hsh[k][ty * 16 + q * 4]);
                ev[2 * q] = ep.x; ev[2 * q + 1] = ep.y;
            }
#pragma unroll
            for (int p = 0; p < 8; ++p)
#pragma unroll
                for (int j = 0; j < 4; ++j)
                    fma2(acc[p][j], ev[p], w2[j]);
        }
    }

#pragma unroll
    for (int p = 0; p < 8; ++p) {
        int na = n0 + ty * 16 + 2 * p;
        float2 v0 = unpack2(acc[p][0]), v1 = unpack2(acc[p][1]);
        float2 v2 = unpack2(acc[p][2]), v3 = unpack2(acc[p][3]);
        if (na < N_NODES)
            *reinterpret_cast<float4*>(dst + (size_t)na * OUT_DIM + tx * 4) =
                make_float4(v0.x, v1.x, v2.x, v3.x);
        if (na + 1 < N_NODES)
            *reinterpret_cast<float4*>(dst + (size_t)(na + 1) * OUT_DIM + tx * 4) =
                make_float4(v0.y, v1.y, v2.y, v3.y);
    }
}

// ---------------------------------------------------------------------------
// Edge kernel: mma.sync bf16-split GEMM + fused gather epilogue.
// Persistent 148 CTAs x 256 threads (8 warps). Block tile 128x128, K=64.
// Warp w owns edges [w*16, w*16+16). 64 f32 accums per thread.
// Smem: bf16 tiles with 144B row stride (conflict-free fragment LDS).
//   B_hi [0, 18432)  B_lo [18432, 36864)
//   A_hi [36864, 55296)  A_lo [55296, 73728)
// ---------------------------------------------------------------------------
#define RS    144                  // row stride bytes
#define SM_BH 0
#define SM_BL 18432
#define SM_AH 36864
#define SM_AL 55296
#define SM_EDGE_TOTAL 73728

__global__ __launch_bounds__(256, 1)
void edge_tc_kernel(const float* __restrict__ e,
                    const int* __restrict__ ei32,
                    const float* __restrict__ We,
                    float* __restrict__ out)
{
    extern __shared__ char smem[];
    const int tid  = threadIdx.x;
    const int wid  = tid >> 5;
    const int lane = tid & 31;
    const int is64 = g_idx_is64;

    const int lr = lane >> 2;        // fragment row/col group 0..7
    const int lc = lane & 3;         // k-pair selector 0..3

    // ---- one-time B fill: We[o][k] f32 -> bf16 hi/lo, rows padded to 144B ----
#pragma unroll
    for (int j = 0; j < 8; ++j) {
        int idx = tid + 256 * j;          // 0..2047 float4s
        int row = idx >> 4;               // o: 0..127
        int q   = idx & 15;               // float4 within row (k = q*4..q*4+3)
        float4 v = reinterpret_cast<const float4*>(We)[idx];
        uint32_t h0, l0, h1, l1;
        cvt_split(v.x, v.y, h0, l0);
        cvt_split(v.z, v.w, h1, l1);
        *reinterpret_cast<u64*>(smem + SM_BH + row * RS + q * 8) = ((u64)h1 << 32) | h0;
        *reinterpret_cast<u64*>(smem + SM_BL + row * RS + q * 8) = ((u64)l1 << 32) | l0;
    }

    // ---- prefetch first tile ----
    int t = blockIdx.x;
    float4 pf[8];
    if (t < NTILES) {
#pragma unroll
        for (int j = 0; j < 8; ++j) {
            int idx = tid + 256 * j;
            int row = idx >> 4;
            int q   = idx & 15;
            pf[j] = *reinterpret_cast<const float4*>(
                e + (size_t)(t * 128 + row) * EDGE_DIM + q * 4);
        }
    }
    __syncthreads();

#pragma unroll 1
    for (; t < NTILES; t += GRID_E) {
        // ---- convert prefetched tile into A smem ----
#pragma unroll
        for (int j = 0; j < 8; ++j) {
            int idx = tid + 256 * j;
            int row = idx >> 4;
            int q   = idx & 15;
            uint32_t h0, l0, h1, l1;
            cvt_split(pf[j].x, pf[j].y, h0, l0);
            cvt_split(pf[j].z, pf[j].w, h1, l1);
            *reinterpret_cast<u64*>(smem + SM_AH + row * RS + q * 8) = ((u64)h1 << 32) | h0;
            *reinterpret_cast<u64*>(smem + SM_AL + row * RS + q * 8) = ((u64)l1 << 32) | l0;
        }
        __syncthreads();

        // ---- prefetch next tile (hidden under MMA + epilogue) ----
        int tn = t + GRID_E;
        if (tn < NTILES) {
#pragma unroll
            for (int j = 0; j < 8; ++j) {
                int idx = tid + 256 * j;
                int row = idx >> 4;
                int q   = idx & 15;
                pf[j] = *reinterpret_cast<const float4*>(
                    e + (size_t)(tn * 128 + row) * EDGE_DIM + q * 4);
            }
        }

        // ---- mainloop: 4 ksteps x 16 ntiles x 3 split-MMAs ----
        float acc[16][4];
#pragma unroll
        for (int j = 0; j < 16; ++j)
#pragma unroll
            for (int c = 0; c < 4; ++c) acc[j][c] = 0.f;

        const int aRow = wid * 16 + lr;          // edge row within tile
        const char* AH = smem + SM_AH;
        const char* AL = smem + SM_AL;
        const char* BH = smem + SM_BH;
        const char* BL = smem + SM_BL;

#pragma unroll
        for (int ks = 0; ks < 4; ++ks) {
            const int kb = ks * 32 + lc * 4;     // byte offset of this lane's k-pair
            uint32_t ah[4], al[4];
            ah[0] = *reinterpret_cast<const uint32_t*>(AH + aRow * RS + kb);
            ah[1] = *reinterpret_cast<const uint32_t*>(AH + (aRow + 8) * RS + kb);
            ah[2] = *reinterpret_cast<const uint32_t*>(AH + aRow * RS + kb + 16);
            ah[3] = *reinterpret_cast<const uint32_t*>(AH + (aRow + 8) * RS + kb + 16);
            al[0] = *reinterpret_cast<const uint32_t*>(AL + aRow * RS + kb);
            al[1] = *reinterpret_cast<const uint32_t*>(AL + (aRow + 8) * RS + kb);
            al[2] = *reinterpret_cast<const uint32_t*>(AL + aRow * RS + kb + 16);
            al[3] = *reinterpret_cast<const uint32_t*>(AL + (aRow + 8) * RS + kb + 16);

#pragma unroll
            for (int j = 0; j < 16; ++j) {
                const int nrow = j * 8 + lr;
                uint32_t bh0 = *reinterpret_cast<const uint32_t*>(BH + nrow * RS + kb);
                uint32_t bh1 = *reinterpret_cast<const uint32_t*>(BH + nrow * RS + kb + 16);
                uint32_t bl0 = *reinterpret_cast<const uint32_t*>(BL + nrow * RS + kb);
                uint32_t bl1 = *reinterpret_cast<const uint32_t*>(BL + nrow * RS + kb + 16);
                mma16816(acc[j], ah, bh0, bh1);   // hi*hi
                mma16816(acc[j], ah, bl0, bl1);   // hi*lo
                mma16816(acc[j], al, bh0, bh1);   // lo*hi
            }
        }

        // ---- epilogue: gather hu[src]+hw[tgt], add, store ----
        const int ea0 = t * 128 + aRow;          // row lr
        const int ea1 = ea0 + 8;                 // row lr+8
        const int s0 = fetch_idx(ei32, is64, (size_t)ea0);
        const int g0 = fetch_idx(ei32, is64, (size_t)N_EDGES + ea0);
        const int s1 = fetch_idx(ei32, is64, (size_t)ea1);
        const int g1 = fetch_idx(ei32, is64, (size_t)N_EDGES + ea1);

        const float* hu0 = g_HU + (size_t)s0 * OUT_DIM;
        const float* hw0 = g_HW + (size_t)g0 * OUT_DIM;
        const float* hu1 = g_HU + (size_t)s1 * OUT_DIM;
        const float* hw1 = g_HW + (size_t)g1 * OUT_DIM;
        float* o0 = out + (size_t)ea0 * OUT_DIM;
        float* o1 = out + (size_t)ea1 * OUT_DIM;

#pragma unroll
        for (int j = 0; j < 16; ++j) {
            const int col = j * 8 + lc * 2;
            float2 A0 = *reinterpret_cast<const float2*>(hu0 + col);
            float2 B0 = *reinterpret_cast<const float2*>(hw0 + col);
            float2 r0 = make_float2(acc[j][0] + A0.x + B0.x, acc[j][1] + A0.y + B0.y);
            *reinterpret_cast<float2*>(o0 + col) = r0;

            float2 A1 = *reinterpret_cast<const float2*>(hu1 + col);
            float2 B1 = *reinterpret_cast<const float2*>(hw1 + col);
            float2 r1 = make_float2(acc[j][2] + A1.x + B1.x, acc[j][3] + A1.y + B1.y);
            *reinterpret_cast<float2*>(o1 + col) = r1;
        }

        __syncthreads();   // A smem reuse barrier
    }
}

extern "C" void kernel_launch(void* const* d_in, const int* in_sizes, int n_in,
                              void* d_out, int out_size)
{
    const float* h   = (const float*)d_in[0];       // [50000,128]
    const float* e   = (const float*)d_in[1];       // [800000,64]
    const int*   ei  = (const int*)d_in[2];         // [2,800000]
    const float* We  = (const float*)d_in[3];       // [128,64]
    const float* Whu = (const float*)d_in[4];       // [128,128]
    const float* Whw = (const float*)d_in[5];       // [128,128]
    float*       out = (float*)d_out;               // [800000,128]

    detect_idx_kernel<<<1, 32>>>(ei);
    dim3 ngrid((N_NODES + 127) / 128, 2);
    node_proj_kernel<<<ngrid, 256>>>(h, Whu, Whw);

    cudaFuncSetAttribute(edge_tc_kernel,
                         cudaFuncAttributeMaxDynamicSharedMemorySize, SM_EDGE_TOTAL);
    edge_tc_kernel<<<GRID_E, 256, SM_EDGE_TOTAL>>>(e, ei, We, out);
}

// round 6
// speedup vs baseline: 1.4660x; 1.4660x over previous
#include <cuda_runtime.h>
#include <cstdint>

#define N_NODES 50000
#define N_EDGES 800000
#define IN_DIM  128
#define OUT_DIM 128
#define EDGE_DIM 64

typedef unsigned long long u64;

// Scratch for node projections (allocation-free per harness rules).
__device__ __align__(16) float g_HU[(size_t)N_NODES * OUT_DIM];
__device__ __align__(16) float g_HW[(size_t)N_NODES * OUT_DIM];
__device__ int g_idx_is64;

__device__ __forceinline__ u64 pack2(float lo, float hi) {
    u64 r; asm("mov.b64 %0, {%1, %2};" : "=l"(r) : "f"(lo), "f"(hi)); return r;
}
__device__ __forceinline__ void fma2(u64& d, u64 a, u64 b) {
    asm("fma.rn.f32x2 %0, %1, %2, %3;" : "=l"(d) : "l"(a), "l"(b), "l"(d));
}
__device__ __forceinline__ float2 unpack2(u64 v) {
    float2 f; asm("mov.b64 {%0, %1}, %2;" : "=f"(f.x), "=f"(f.y) : "l"(v)); return f;
}

// ---------------------------------------------------------------------------
// Index-dtype detection (int32 vs int64 edge_index), deterministic per call.
// ---------------------------------------------------------------------------
__global__ void detect_idx_kernel(const int* __restrict__ ei32) {
    if (threadIdx.x == 0 && blockIdx.x == 0) {
        int all_zero = 1;
        for (int i = 0; i < 256; ++i)
            if (ei32[2 * i + 1] != 0) { all_zero = 0; break; }
        g_idx_is64 = all_zero;
    }
}
__device__ __forceinline__ int fetch_idx(const int* __restrict__ ei32,
                                         int is64, size_t pos) {
    int v = is64 ? ei32[2 * pos] : ei32[pos];
    v = v < 0 ? 0 : (v >= N_NODES ? N_NODES - 1 : v);
    return v;
}

// ---------------------------------------------------------------------------
// Node projection (both W_hu and W_hw via blockIdx.y) — proven R3 kernel.
// ---------------------------------------------------------------------------
__global__ __launch_bounds__(256, 2)
void node_proj_kernel(const float* __restrict__ h,
                      const float* __restrict__ Whu,
                      const float* __restrict__ Whw)
{
    __shared__ __align__(16) float Wsh[32][132];
    __shared__ __align__(16) float Hsh[32][132];

    const float* __restrict__ W   = blockIdx.y ? Whw : Whu;
    float*       __restrict__ dst = blockIdx.y ? g_HW : g_HU;

    const int tid = threadIdx.x;
    const int tx  = tid & 31;
    const int ty  = tid >> 5;
    const int n0  = blockIdx.x * 128;

    u64 acc[8][4];
#pragma unroll
    for (int p = 0; p < 8; ++p)
#pragma unroll
        for (int j = 0; j < 4; ++j) acc[p][j] = 0ULL;

#pragma unroll 1
    for (int s = 0; s < 4; ++s) {
        __syncthreads();
#pragma unroll
        for (int it = 0; it < 4; ++it) {
            int idx = it * 256 + tid;
            int o   = idx >> 3;
            int kq  = idx & 7;
            float4 w = *reinterpret_cast<const float4*>(W + (size_t)o * IN_DIM + s * 32 + kq * 4);
            Wsh[kq * 4 + 0][o] = w.x; Wsh[kq * 4 + 1][o] = w.y;
            Wsh[kq * 4 + 2][o] = w.z; Wsh[kq * 4 + 3][o] = w.w;
        }
#pragma unroll
        for (int it = 0; it < 4; ++it) {
            int idx = it * 256 + tid;
            int ln  = idx >> 3;
            int kq  = idx & 7;
            int n   = n0 + ln;
            float4 v = make_float4(0.f, 0.f, 0.f, 0.f);
            if (n < N_NODES)
                v = *reinterpret_cast<const float4*>(h + (size_t)n * IN_DIM + s * 32 + kq * 4);
            Hsh[kq * 4 + 0][ln] = v.x; Hsh[kq * 4 + 1][ln] = v.y;
            Hsh[kq * 4 + 2][ln] = v.z; Hsh[kq * 4 + 3][ln] = v.w;
        }
        __syncthreads();

#pragma unroll
        for (int k = 0; k < 32; ++k) {
            float4 w = *reinterpret_cast<const float4*>(&Wsh[k][tx * 4]);
            u64 w2[4];
            w2[0] = pack2(w.x, w.x); w2[1] = pack2(w.y, w.y);
            w2[2] = pack2(w.z, w.z); w2[3] = pack2(w.w, w.w);
            u64 ev[8];
#pragma unroll
            for (int q = 0; q < 4; ++q) {
                ulonglong2 ep = *reinterpret_cast<const ulonglong2*>(&Hsh[k][ty * 16 + q * 4]);
                ev[2 * q] = ep.x; ev[2 * q + 1] = ep.y;
            }
#pragma unroll
            for (int p = 0; p < 8; ++p)
#pragma unroll
                for (int j = 0; j < 4; ++j)
                    fma2(acc[p][j], ev[p], w2[j]);
        }
    }

#pragma unroll
    for (int p = 0; p < 8; ++p) {
        int na = n0 + ty * 16 + 2 * p;
        float2 v0 = unpack2(acc[p][0]), v1 = unpack2(acc[p][1]);
        float2 v2 = unpack2(acc[p][2]), v3 = unpack2(acc[p][3]);
        if (na < N_NODES)
            *reinterpret_cast<float4*>(dst + (size_t)na * OUT_DIM + tx * 4) =
                make_float4(v0.x, v1.x, v2.x, v3.x);
        if (na + 1 < N_NODES)
            *reinterpret_cast<float4*>(dst + (size_t)(na + 1) * OUT_DIM + tx * 4) =
                make_float4(v0.y, v1.y, v2.y, v3.y);
    }
}

// ---------------------------------------------------------------------------
// Fused edge kernel v2: out[eid][o] = sum_k e[eid][k]*We[o][k] + hu[src][o] + hw[tgt][o]
// Block tile 128 edges x 64 outs (grid 6250 x 2) -> occupancy 3.
// Thread tile 8 edges x 4 outs (32 accum regs). K=64 staged by 16 with
// register prefetch of the next stage.
// ---------------------------------------------------------------------------
__global__ __launch_bounds__(256, 3)
void edge_kernel(const float* __restrict__ e,
                 const int* __restrict__ ei32,
                 const float* __restrict__ We,
                 float* __restrict__ out)
{
    __shared__ __align__(16) float Wsh[EDGE_DIM][68];   // [k][o-half]  ~17.4KB
    __shared__ __align__(16) float Esh[16][132];        // [k][edge]     ~8.4KB

    const int tid  = threadIdx.x;
    const int tx   = tid & 15;   // outs: oh + tx*4 .. +3
    const int ty   = tid >> 4;   // edges: ty*8 .. ty*8+7
    const int e0   = blockIdx.x * 128;
    const int oh   = blockIdx.y * 64;
    const int is64 = g_idx_is64;

    // One-time W fill (transposed mapping -> conflict-free STS; LDG hits L2).
    // idx: o = idx & 63, kq = idx >> 6 (16 values -> 1024 float4s total)
#pragma unroll
    for (int it = 0; it < 4; ++it) {
        int idx = it * 256 + tid;       // 0..1023
        int o   = idx & 63;
        int kq  = idx >> 6;             // 0..15
        float4 w = *reinterpret_cast<const float4*>(
            We + (size_t)(oh + o) * EDGE_DIM + kq * 4);
        Wsh[kq * 4 + 0][o] = w.x;
        Wsh[kq * 4 + 1][o] = w.y;
        Wsh[kq * 4 + 2][o] = w.z;
        Wsh[kq * 4 + 3][o] = w.w;
    }

    u64 acc[4][4];
#pragma unroll
    for (int p = 0; p < 4; ++p)
#pragma unroll
        for (int j = 0; j < 4; ++j) acc[p][j] = 0ULL;

    // E stage fill: thread covers float4 idx {tid, 256+tid} of 512 per stage
    const int le0 = tid >> 2,         kq0 = tid & 3;
    const int le1 = (256 + tid) >> 2, kq1 = (256 + tid) & 3;

    float4 pf0, pf1;
    pf0 = *reinterpret_cast<const float4*>(e + (size_t)(e0 + le0) * EDGE_DIM + kq0 * 4);
    pf1 = *reinterpret_cast<const float4*>(e + (size_t)(e0 + le1) * EDGE_DIM + kq1 * 4);
    Esh[kq0 * 4 + 0][le0] = pf0.x; Esh[kq0 * 4 + 1][le0] = pf0.y;
    Esh[kq0 * 4 + 2][le0] = pf0.z; Esh[kq0 * 4 + 3][le0] = pf0.w;
    Esh[kq1 * 4 + 0][le1] = pf1.x; Esh[kq1 * 4 + 1][le1] = pf1.y;
    Esh[kq1 * 4 + 2][le1] = pf1.z; Esh[kq1 * 4 + 3][le1] = pf1.w;
    __syncthreads();

#pragma unroll 1
    for (int s = 0; s < 4; ++s) {
        if (s < 3) {  // prefetch next stage into registers
            pf0 = *reinterpret_cast<const float4*>(
                e + (size_t)(e0 + le0) * EDGE_DIM + (s + 1) * 16 + kq0 * 4);
            pf1 = *reinterpret_cast<const float4*>(
                e + (size_t)(e0 + le1) * EDGE_DIM + (s + 1) * 16 + kq1 * 4);
        }

#pragma unroll
        for (int k = 0; k < 16; ++k) {
            int kk = s * 16 + k;
            float4 w = *reinterpret_cast<const float4*>(&Wsh[kk][tx * 4]);
            u64 w2[4];
            w2[0] = pack2(w.x, w.x); w2[1] = pack2(w.y, w.y);
            w2[2] = pack2(w.z, w.z); w2[3] = pack2(w.w, w.w);
            u64 ev[4];
            {
                ulonglong2 ea = *reinterpret_cast<const ulonglong2*>(&Esh[k][ty * 8]);
                ulonglong2 eb = *reinterpret_cast<const ulonglong2*>(&Esh[k][ty * 8 + 4]);
                ev[0] = ea.x; ev[1] = ea.y; ev[2] = eb.x; ev[3] = eb.y;
            }
#pragma unroll
            for (int p = 0; p < 4; ++p)
#pragma unroll
                for (int j = 0; j < 4; ++j)
                    fma2(acc[p][j], ev[p], w2[j]);
        }

        if (s < 3) {
            __syncthreads();
            Esh[kq0 * 4 + 0][le0] = pf0.x; Esh[kq0 * 4 + 1][le0] = pf0.y;
            Esh[kq0 * 4 + 2][le0] = pf0.z; Esh[kq0 * 4 + 3][le0] = pf0.w;
            Esh[kq1 * 4 + 0][le1] = pf1.x; Esh[kq1 * 4 + 1][le1] = pf1.y;
            Esh[kq1 * 4 + 2][le1] = pf1.z; Esh[kq1 * 4 + 3][le1] = pf1.w;
            __syncthreads();
        }
    }

    // Epilogue: gather hu[src], hw[tgt] (L2-resident), coalesced float4 stores.
#pragma unroll
    for (int p = 0; p < 4; ++p) {
        int ea = e0 + ty * 8 + 2 * p;   // edge pair (ea, ea+1)
        int sa = fetch_idx(ei32, is64, (size_t)ea);
        int ta = fetch_idx(ei32, is64, (size_t)N_EDGES + ea);
        int sb = fetch_idx(ei32, is64, (size_t)ea + 1);
        int tb = fetch_idx(ei32, is64, (size_t)N_EDGES + ea + 1);

        float2 v0 = unpack2(acc[p][0]), v1 = unpack2(acc[p][1]);
        float2 v2 = unpack2(acc[p][2]), v3 = unpack2(acc[p][3]);

        float4 A = *reinterpret_cast<const float4*>(g_HU + (size_t)sa * OUT_DIM + oh + tx * 4);
        float4 B = *reinterpret_cast<const float4*>(g_HW + (size_t)ta * OUT_DIM + oh + tx * 4);
        *reinterpret_cast<float4*>(out + (size_t)ea * OUT_DIM + oh + tx * 4) =
            make_float4(v0.x + A.x + B.x, v1.x + A.y + B.y,
                        v2.x + A.z + B.z, v3.x + A.w + B.w);

        float4 C = *reinterpret_cast<const float4*>(g_HU + (size_t)sb * OUT_DIM + oh + tx * 4);
        float4 D = *reinterpret_cast<const float4*>(g_HW + (size_t)tb * OUT_DIM + oh + tx * 4);
        *reinterpret_cast<float4*>(out + (size_t)(ea + 1) * OUT_DIM + oh + tx * 4) =
            make_float4(v0.y + C.x + D.x, v1.y + C.y + D.y,
                        v2.y + C.z + D.z, v3.y + C.w + D.w);
    }
}

extern "C" void kernel_launch(void* const* d_in, const int* in_sizes, int n_in,
                              void* d_out, int out_size)
{
    const float* h   = (const float*)d_in[0];       // [50000,128]
    const float* e   = (const float*)d_in[1];       // [800000,64]
    const int*   ei  = (const int*)d_in[2];         // [2,800000]
    const float* We  = (const float*)d_in[3];       // [128,64]
    const float* Whu = (const float*)d_in[4];       // [128,128]
    const float* Whw = (const float*)d_in[5];       // [128,128]
    float*       out = (float*)d_out;               // [800000,128]

    detect_idx_kernel<<<1, 32>>>(ei);
    dim3 ngrid((N_NODES + 127) / 128, 2);
    node_proj_kernel<<<ngrid, 256>>>(h, Whu, Whw);
    dim3 egrid(N_EDGES / 128, 2);
    edge_kernel<<<egrid, 256>>>(e, ei, We, out);
}